// round 11
// baseline (speedup 1.0000x reference)
#include <cuda_runtime.h>
#include <math.h>

// Problem shape (fixed for this dataset instance)
#define NB   4
#define NT   512
#define NVOC 8000
#define NH   7
#define BT   (NB * NT)           // 2048

#define LCH  32
#define NCH  (NT / LCH)          // 16

#define TPB    160
#define VTILES (NVOC / TPB)      // 50

// epilogue shape: float4 columns, 8000/4 = 2000 = 20 * 100
#define ETPB   100
#define EVT    20

#define ROWS 16                  // distinct-token rows per k_dist block
#define EPSR 1e-12f

typedef unsigned long long ull;

// ---------------- f32x2 packed helpers (sm_103a native) --------------
__device__ __forceinline__ ull pk2(float lo, float hi) {
    ull r; asm("mov.b64 %0, {%1, %2};" : "=l"(r) : "f"(lo), "f"(hi)); return r;
}
__device__ __forceinline__ float2 upk2(ull a) {
    float2 r; asm("mov.b64 {%0, %1}, %2;" : "=f"(r.x), "=f"(r.y) : "l"(a)); return r;
}
__device__ __forceinline__ ull add2_(ull a, ull b) {
    ull r; asm("add.rn.f32x2 %0, %1, %2;" : "=l"(r) : "l"(a), "l"(b)); return r;
}
__device__ __forceinline__ ull mul2_(ull a, ull b) {
    ull r; asm("mul.rn.f32x2 %0, %1, %2;" : "=l"(r) : "l"(a), "l"(b)); return r;
}
__device__ __forceinline__ ull fma2_(ull a, ull b, ull c) {
    ull r; asm("fma.rn.f32x2 %0, %1, %2, %3;" : "=l"(r) : "l"(a), "l"(b), "l"(c)); return r;
}
__device__ __forceinline__ float rcpf(float x) {
    float r; asm("rcp.approx.ftz.f32 %0, %1;" : "=f"(r) : "f"(x)); return r;
}
__device__ __forceinline__ ull rcp2_(ull a) {
    float2 t = upk2(a); return pk2(rcpf(t.x), rcpf(t.y));
}

// ---------------- device scratch (no allocs allowed) ----------------
__device__ float gVnF[NH * NVOC];        // -(2*pi*f_v*h')
__device__ float gVS[NH * NVOC];         // 2*A_vh' * sin(F)
__device__ float gVC[NH * NVOC];         // 2*A_vh' * cos(F)
// distinct-token table, comp-major [24][BT]:
// 0..6 F, 7..13 A*sin, 14..20 -A*cos, 21 dv, 22 token-as-bits, 23 pad
__device__ float gTC[24 * BT];
__device__ int   gMap[NVOC];             // token -> compact id (-1 none, -2 marked)
__device__ int   gCnt;                   // number of distinct tokens this run
__device__ float gK[(size_t)BT * NVOC];  // K[xid][v] table (worst case 65.5 MB)
__device__ float gCS[NB * NCH * NVOC];   // per-chunk totals

// ---------------- 0: reset + mark in one single-block kernel ---------
__global__ void k_init(const int* __restrict__ ids) {
    int tid = threadIdx.x;
    for (int i = tid; i < NVOC; i += blockDim.x) gMap[i] = -1;
    if (tid == 0) gCnt = 0;
    __syncthreads();                     // reset complete before marking
    for (int i = tid; i < BT; i += blockDim.x) gMap[ids[i]] = -2;
}

// ---------------- 1: vocab tables + compact ids + token tables -------
// trig: exact double range reduction (3 DP ops) + float sinpi/cospi —
// avoids the FP64 sincos software path entirely.
__global__ void k_prep(const float* __restrict__ freq,
                       const float* __restrict__ amp,
                       const float* __restrict__ decay) {
    int v = blockIdx.x * blockDim.x + threadIdx.x;
    if (v >= NVOC) return;
    float f = freq[v], A = amp[v], dec = decay[0];
    // log2(h) for h = 1..7 (compile-time constants)
    const float L2H[NH] = {0.f, 1.f, 1.5849625007f, 2.f,
                           2.3219280949f, 2.5849625007f, 2.8073549221f};
    double fd = (double)f;
    float Fh[NH], Sh[NH], Ch[NH];
    float dv = 0.f;
#pragma unroll
    for (int h = 1; h <= NH; h++) {
        double x = fd * (double)h;
        double r = x - rint(x);              // exact frac in [-0.5, 0.5]
        float rf = 2.0f * (float)r;
        float s = sinpif(rf);                // sin(2*pi*f*h)
        float c = cospif(rf);
        float F = (float)(6.283185307179586 * x);
        float Ah2 = 2.0f * A * exp2f(-dec * L2H[h - 1]);  // 2*A/h^dec
        int i = (h - 1) * NVOC + v;
        float vs = Ah2 * s, vc = Ah2 * c;
        gVnF[i] = -F;
        gVS[i]  = vs;
        gVC[i]  = vc;
        Fh[h - 1] = F;
        Sh[h - 1] = 0.5f * vs;       // A*sin (token side, no factor 2)
        Ch[h - 1] = -0.5f * vc;      // -A*cos
        dv += 0.5f * Ah2 * Ah2;      // sum_h 2*(A/h^dec)^2
    }
    if (gMap[v] == -2) {             // this vocab entry occurs as a token
        int id = atomicAdd(&gCnt, 1);
        gMap[v] = id;
#pragma unroll
        for (int h = 0; h < NH; h++) {
            gTC[h * BT + id]        = Fh[h];
            gTC[(7 + h) * BT + id]  = Sh[h];
            gTC[(14 + h) * BT + id] = Ch[h];
        }
        gTC[21 * BT + id] = dv;
        gTC[22 * BT + id] = __int_as_float(v);
    }
}

// ---------------- 2: heavy kernel — K[xid][v] for distinct tokens ----
// grid = (VTILES, BT/ROWS), block = TPB. Thread owns vocab column v,
// f32x2-packed over token-row pairs. 35 coprime (h,g) "base" pairs get a
// full regularized reciprocal; the 14 harmonic multiples (kh0,kg0) reuse
// the base's w = d/(d^2+eps) via term_k = n_k*(1/k)*w (D scales exactly
// by k up to float rounding; error ~1e-5 rel, calibrated R3->R4).
// ROWS=16: ~5700 active blocks smooths per-SM wave imbalance.
__global__ __launch_bounds__(TPB) void k_dist() {
    __shared__ __align__(16) float st[24 * ROWS];
    int base = blockIdx.y * ROWS;
    int cnt = gCnt;
    if (base >= cnt) return;
    int v = blockIdx.x * TPB + threadIdx.x;   // always < NVOC (exact tiling)

    // stage 24 comps x ROWS rows (comp-major both sides), vectorized
    for (int i = threadIdx.x; i < 24 * ROWS / 4; i += TPB) {
        int comp = i / (ROWS / 4), q = i % (ROWS / 4);
        ((float4*)st)[i] = ((const float4*)(gTC + comp * BT + base))[q];
    }

    // vocab-side values: broadcast-packed registers
    ull vF[NH], vS[NH], vC[NH];
#pragma unroll
    for (int g = 0; g < NH; g++) {
        float nf = gVnF[g * NVOC + v];
        float s  = gVS[g * NVOC + v];
        float cc = gVC[g * NVOC + v];
        vF[g] = pk2(nf, nf);
        vS[g] = pk2(s, s);
        vC[g] = pk2(cc, cc);
    }
    const ull E2  = pk2(EPSR, EPSR);
    const ull IV2 = pk2(0.5f, 0.5f);
    const ull IV3 = pk2(1.f / 3.f, 1.f / 3.f);
    const ull IV4 = pk2(0.25f, 0.25f);
    const ull IV5 = pk2(0.2f, 0.2f);
    const ull IV6 = pk2(1.f / 6.f, 1.f / 6.f);
    const ull IV7 = pk2(1.f / 7.f, 1.f / 7.f);
    __syncthreads();

    for (int p = 0; p < ROWS / 2; p++) {
        int r0 = base + 2 * p;
        if (r0 >= cnt) break;

        auto FX  = [&](int h) { return *(const ull*)(st + (h - 1) * ROWS + 2 * p); };
        auto TS  = [&](int h) { return *(const ull*)(st + (7 + h - 1) * ROWS + 2 * p); };
        auto TCN = [&](int h) { return *(const ull*)(st + (14 + h - 1) * ROWS + 2 * p); };
        auto nOf = [&](int h, int g) {
            return fma2_(TS(h), vC[g - 1], mul2_(TCN(h), vS[g - 1]));
        };
        // plain base: S += n*d/(d^2+eps)
        auto baseT = [&](int h, int g, ull& S) {
            ull d   = add2_(FX(h), vF[g - 1]);
            ull n   = nOf(h, g);
            ull den = fma2_(d, d, E2);
            S = fma2_(mul2_(n, d), rcp2_(den), S);
        };
        // base exporting w = d/(d^2+eps): S += n*w
        auto baseW = [&](int h, int g, ull& S) -> ull {
            ull d   = add2_(FX(h), vF[g - 1]);
            ull n   = nOf(h, g);
            ull den = fma2_(d, d, E2);
            ull w   = mul2_(d, rcp2_(den));
            S = fma2_(n, w, S);
            return w;
        };

        ull Sa = pk2(0.f, 0.f), Sb = pk2(0.f, 0.f);

        // ---- h = 1 ----
        ull w11 = baseW(1, 1, Sa);
        ull w12 = baseW(1, 2, Sb);
        ull w13 = baseW(1, 3, Sa);
        baseT(1, 4, Sb); baseT(1, 5, Sa); baseT(1, 6, Sb); baseT(1, 7, Sa);
        // ---- h = 2 ----
        ull w21 = baseW(2, 1, Sb);
        ull w23 = baseW(2, 3, Sa);
        baseT(2, 5, Sb); baseT(2, 7, Sa);
        ull G11 = mul2_(nOf(2, 2), IV2);                      // 2*(1,1)
        ull G12 = mul2_(nOf(2, 4), IV2);                      // 2*(1,2)
        Sb = fma2_(mul2_(nOf(2, 6), IV2), w13, Sb);           // 2*(1,3)
        // ---- h = 3 ----
        ull w31 = baseW(3, 1, Sa);
        ull w32 = baseW(3, 2, Sb);
        baseT(3, 4, Sa); baseT(3, 5, Sb); baseT(3, 7, Sa);
        G11 = fma2_(nOf(3, 3), IV3, G11);                     // 3*(1,1)
        G12 = fma2_(nOf(3, 6), IV3, G12);                     // 3*(1,2)
        Sb = fma2_(G12, w12, Sb);                             // finalize (1,2) group
        // ---- h = 4 ----
        baseT(4, 1, Sa); baseT(4, 3, Sb); baseT(4, 5, Sa); baseT(4, 7, Sb);
        ull G21 = mul2_(nOf(4, 2), IV2);                      // 2*(2,1)
        G11 = fma2_(nOf(4, 4), IV4, G11);                     // 4*(1,1)
        Sa = fma2_(mul2_(nOf(4, 6), IV2), w23, Sa);           // 2*(2,3)
        // ---- h = 5 ----
        baseT(5, 1, Sb); baseT(5, 2, Sa); baseT(5, 3, Sb);
        baseT(5, 4, Sa); baseT(5, 6, Sb); baseT(5, 7, Sa);
        G11 = fma2_(nOf(5, 5), IV5, G11);                     // 5*(1,1)
        // ---- h = 6 ----
        baseT(6, 1, Sb); baseT(6, 5, Sa); baseT(6, 7, Sb);
        Sa = fma2_(mul2_(nOf(6, 2), IV2), w31, Sa);           // 2*(3,1)
        G21 = fma2_(nOf(6, 3), IV3, G21);                     // 3*(2,1)
        Sb = fma2_(G21, w21, Sb);                             // finalize (2,1) group
        Sa = fma2_(mul2_(nOf(6, 4), IV2), w32, Sa);           // 2*(3,2)
        G11 = fma2_(nOf(6, 6), IV6, G11);                     // 6*(1,1)
        // ---- h = 7 ----
        baseT(7, 1, Sa); baseT(7, 2, Sb); baseT(7, 3, Sa);
        baseT(7, 4, Sb); baseT(7, 5, Sa); baseT(7, 6, Sb);
        G11 = fma2_(nOf(7, 7), IV7, G11);                     // 7*(1,1)
        Sa = fma2_(G11, w11, Sa);                             // finalize (1,1) group

        ull S = add2_(Sa, Sb);
        float2 s2 = upk2(S);
        int tok0 = __float_as_int(st[22 * ROWS + 2 * p]);
        int tok1 = __float_as_int(st[22 * ROWS + 2 * p + 1]);
        float k0 = s2.x + ((tok0 == v) ? st[21 * ROWS + 2 * p] : 0.f);
        gK[(size_t)r0 * NVOC + v] = k0;
        if (r0 + 1 < cnt) {
            float k1 = s2.y + ((tok1 == v) ? st[21 * ROWS + 2 * p + 1] : 0.f);
            gK[(size_t)(r0 + 1) * NVOC + v] = k1;
        }
    }
}

// ---------------- 3: chunk totals (float4 gathers from K) ------------
// grid (EVT, NCH-1, NB) = 1200 blocks of 100 threads. Thread owns 4
// consecutive v. More blocks -> more in-flight loads -> higher DRAM%.
__global__ __launch_bounds__(ETPB) void k_ctot(const int* __restrict__ ids) {
    __shared__ int xid[LCH];
    int b = blockIdx.z, c = blockIdx.y;
    int v4 = blockIdx.x * ETPB + threadIdx.x;   // < 2000 (exact)
    if (threadIdx.x < LCH)
        xid[threadIdx.x] = gMap[ids[b * NT + c * LCH + threadIdx.x]];
    __syncthreads();
    float4 s = make_float4(0.f, 0.f, 0.f, 0.f);
#pragma unroll 1
    for (int t0 = 0; t0 < LCH; t0 += 8) {
        float4 vb[8];
#pragma unroll
        for (int j = 0; j < 8; j++)
            vb[j] = *(const float4*)(gK + (size_t)xid[t0 + j] * NVOC + 4 * v4);
#pragma unroll
        for (int j = 0; j < 8; j++) {
            s.x += vb[j].x; s.y += vb[j].y; s.z += vb[j].z; s.w += vb[j].w;
        }
    }
    *(float4*)(gCS + (size_t)(b * NCH + c) * NVOC + 4 * v4) = s;
}

// ---------------- 4: final — float4 gathers + cumsum + offsets -------
// grid (EVT, NCH, NB) = 1280 blocks of 100 threads.
__global__ __launch_bounds__(ETPB) void k_final(float* __restrict__ out,
                                                const int* __restrict__ ids) {
    __shared__ int xid[LCH];
    int b = blockIdx.z, c = blockIdx.y;
    int v4 = blockIdx.x * ETPB + threadIdx.x;
    if (threadIdx.x < LCH)
        xid[threadIdx.x] = gMap[ids[b * NT + c * LCH + threadIdx.x]];
    __syncthreads();
    float4 acc = make_float4(0.f, 0.f, 0.f, 0.f);
#pragma unroll 1
    for (int cp = 0; cp < c; cp++) {          // <=15 independent loads
        float4 o = *(const float4*)(gCS + (size_t)(b * NCH + cp) * NVOC + 4 * v4);
        acc.x += o.x; acc.y += o.y; acc.z += o.z; acc.w += o.w;
    }
    float* op = out + ((size_t)(b * NT + c * LCH)) * NVOC + 4 * v4;
#pragma unroll 1
    for (int t0 = 0; t0 < LCH; t0 += 8) {
        float4 vb[8];
#pragma unroll
        for (int j = 0; j < 8; j++)
            vb[j] = *(const float4*)(gK + (size_t)xid[t0 + j] * NVOC + 4 * v4);
#pragma unroll
        for (int j = 0; j < 8; j++) {
            *(float4*)op = acc; op += NVOC;
            acc.x += vb[j].x; acc.y += vb[j].y; acc.z += vb[j].z; acc.w += vb[j].w;
        }
    }
}

// ---------------- launch ---------------------------------------------
extern "C" void kernel_launch(void* const* d_in, const int* in_sizes, int n_in,
                              void* d_out, int out_size) {
    const int*   ids   = (const int*)d_in[0];
    const float* freq  = (const float*)d_in[1];
    const float* amp   = (const float*)d_in[2];
    const float* decay = (const float*)d_in[3];
    // d_in[4] = chunk_size: affects only reference's internal map chunking; result-invariant.
    float* out = (float*)d_out;

    k_init<<<1, 1024>>>(ids);                               // 0
    k_prep<<<(NVOC + 127) / 128, 128>>>(freq, amp, decay);  // 1

    dim3 gdist(VTILES, BT / ROWS);
    k_dist<<<gdist, TPB>>>();                               // 2

    dim3 gct(EVT, NCH - 1, NB);
    k_ctot<<<gct, ETPB>>>(ids);                             // 3 <- profiled slot

    dim3 gfin(EVT, NCH, NB);
    k_final<<<gfin, ETPB>>>(out, ids);                      // 4
}

// round 12
// speedup vs baseline: 1.0177x; 1.0177x over previous
#include <cuda_runtime.h>
#include <math.h>

// Problem shape (fixed for this dataset instance)
#define NB   4
#define NT   512
#define NVOC 8000
#define NH   7
#define BT   (NB * NT)           // 2048

#define LCH  64                  // k_final chunk length
#define NCH  (NT / LCH)          // 8
#define HCH  32                  // k_ctot half-chunk length
#define NHC  (NT / HCH)          // 16 (last 2 halves never consumed)

#define TPB    160
#define VTILES (NVOC / TPB)      // 50

// epilogue shape: float4 columns, 8000/4 = 2000 = 10 * 200
#define ETPB   200
#define EVT    10

#define ROWS 32                  // distinct-token rows per k_dist block
#define EPSR 1e-12f

typedef unsigned long long ull;

// ---------------- f32x2 packed helpers (sm_103a native) --------------
__device__ __forceinline__ ull pk2(float lo, float hi) {
    ull r; asm("mov.b64 %0, {%1, %2};" : "=l"(r) : "f"(lo), "f"(hi)); return r;
}
__device__ __forceinline__ float2 upk2(ull a) {
    float2 r; asm("mov.b64 {%0, %1}, %2;" : "=f"(r.x), "=f"(r.y) : "l"(a)); return r;
}
__device__ __forceinline__ ull add2_(ull a, ull b) {
    ull r; asm("add.rn.f32x2 %0, %1, %2;" : "=l"(r) : "l"(a), "l"(b)); return r;
}
__device__ __forceinline__ ull mul2_(ull a, ull b) {
    ull r; asm("mul.rn.f32x2 %0, %1, %2;" : "=l"(r) : "l"(a), "l"(b)); return r;
}
__device__ __forceinline__ ull fma2_(ull a, ull b, ull c) {
    ull r; asm("fma.rn.f32x2 %0, %1, %2, %3;" : "=l"(r) : "l"(a), "l"(b), "l"(c)); return r;
}
__device__ __forceinline__ float rcpf(float x) {
    float r; asm("rcp.approx.ftz.f32 %0, %1;" : "=f"(r) : "f"(x)); return r;
}
__device__ __forceinline__ ull rcp2_(ull a) {
    float2 t = upk2(a); return pk2(rcpf(t.x), rcpf(t.y));
}

// ---------------- device scratch (no allocs allowed) ----------------
__device__ float gVnF[NH * NVOC];        // -(2*pi*f_v*h')
__device__ float gVS[NH * NVOC];         // 2*A_vh' * sin(F)
__device__ float gVC[NH * NVOC];         // 2*A_vh' * cos(F)
// distinct-token table, comp-major [24][BT]:
// 0..6 F, 7..13 A*sin, 14..20 -A*cos, 21 dv, 22 token-as-bits, 23 pad
__device__ float gTC[24 * BT];
__device__ int   gMap[NVOC];             // token -> compact id (-1 none, -2 marked)
__device__ int   gCnt;                   // number of distinct tokens this run
__device__ float gK[(size_t)BT * NVOC];  // K[xid][v] table (worst case 65.5 MB)
__device__ float gCS[NB * NHC * NVOC];   // per-HALF-chunk totals

// ---------------- 0: reset + mark in one single-block kernel ---------
__global__ void k_init(const int* __restrict__ ids) {
    int tid = threadIdx.x;
    for (int i = tid; i < NVOC; i += blockDim.x) gMap[i] = -1;
    if (tid == 0) gCnt = 0;
    __syncthreads();                     // reset complete before marking
    for (int i = tid; i < BT; i += blockDim.x) gMap[ids[i]] = -2;
}

// ---------------- 1: vocab tables + compact ids + token tables -------
// trig: exact double range reduction (3 DP ops) + float sinpi/cospi —
// avoids the FP64 sincos software path entirely.
__global__ void k_prep(const float* __restrict__ freq,
                       const float* __restrict__ amp,
                       const float* __restrict__ decay) {
    int v = blockIdx.x * blockDim.x + threadIdx.x;
    if (v >= NVOC) return;
    float f = freq[v], A = amp[v], dec = decay[0];
    // log2(h) for h = 1..7 (compile-time constants)
    const float L2H[NH] = {0.f, 1.f, 1.5849625007f, 2.f,
                           2.3219280949f, 2.5849625007f, 2.8073549221f};
    double fd = (double)f;
    float Fh[NH], Sh[NH], Ch[NH];
    float dv = 0.f;
#pragma unroll
    for (int h = 1; h <= NH; h++) {
        double x = fd * (double)h;
        double r = x - rint(x);              // exact frac in [-0.5, 0.5]
        float rf = 2.0f * (float)r;
        float s = sinpif(rf);                // sin(2*pi*f*h)
        float c = cospif(rf);
        float F = (float)(6.283185307179586 * x);
        float Ah2 = 2.0f * A * exp2f(-dec * L2H[h - 1]);  // 2*A/h^dec
        int i = (h - 1) * NVOC + v;
        float vs = Ah2 * s, vc = Ah2 * c;
        gVnF[i] = -F;
        gVS[i]  = vs;
        gVC[i]  = vc;
        Fh[h - 1] = F;
        Sh[h - 1] = 0.5f * vs;       // A*sin (token side, no factor 2)
        Ch[h - 1] = -0.5f * vc;      // -A*cos
        dv += 0.5f * Ah2 * Ah2;      // sum_h 2*(A/h^dec)^2
    }
    if (gMap[v] == -2) {             // this vocab entry occurs as a token
        int id = atomicAdd(&gCnt, 1);
        gMap[v] = id;
#pragma unroll
        for (int h = 0; h < NH; h++) {
            gTC[h * BT + id]        = Fh[h];
            gTC[(7 + h) * BT + id]  = Sh[h];
            gTC[(14 + h) * BT + id] = Ch[h];
        }
        gTC[21 * BT + id] = dv;
        gTC[22 * BT + id] = __int_as_float(v);
    }
}

// ---------------- 2: heavy kernel — K[xid][v] for distinct tokens ----
// grid = (VTILES, BT/ROWS), block = TPB. Thread owns vocab column v,
// f32x2-packed over token-row pairs. 35 coprime (h,g) "base" pairs get a
// full regularized reciprocal; the 14 harmonic multiples (kh0,kg0) reuse
// the base's w = d/(d^2+eps) via term_k = n_k*(1/k)*w (D scales exactly
// by k up to float rounding; error ~1e-5 rel, calibrated R3->R4).
__global__ __launch_bounds__(TPB) void k_dist() {
    __shared__ __align__(16) float st[24 * ROWS];
    int base = blockIdx.y * ROWS;
    int cnt = gCnt;
    if (base >= cnt) return;
    int v = blockIdx.x * TPB + threadIdx.x;   // always < NVOC (exact tiling)

    // stage 24 comps x ROWS rows (comp-major both sides), vectorized
    for (int i = threadIdx.x; i < 24 * ROWS / 4; i += TPB) {
        int comp = i >> 3, q = i & 7;         // ROWS/4 == 8
        ((float4*)st)[i] = ((const float4*)(gTC + comp * BT + base))[q];
    }

    // vocab-side values: broadcast-packed registers
    ull vF[NH], vS[NH], vC[NH];
#pragma unroll
    for (int g = 0; g < NH; g++) {
        float nf = gVnF[g * NVOC + v];
        float s  = gVS[g * NVOC + v];
        float cc = gVC[g * NVOC + v];
        vF[g] = pk2(nf, nf);
        vS[g] = pk2(s, s);
        vC[g] = pk2(cc, cc);
    }
    const ull E2  = pk2(EPSR, EPSR);
    const ull IV2 = pk2(0.5f, 0.5f);
    const ull IV3 = pk2(1.f / 3.f, 1.f / 3.f);
    const ull IV4 = pk2(0.25f, 0.25f);
    const ull IV5 = pk2(0.2f, 0.2f);
    const ull IV6 = pk2(1.f / 6.f, 1.f / 6.f);
    const ull IV7 = pk2(1.f / 7.f, 1.f / 7.f);
    __syncthreads();

    for (int p = 0; p < ROWS / 2; p++) {
        int r0 = base + 2 * p;
        if (r0 >= cnt) break;

        auto FX  = [&](int h) { return *(const ull*)(st + (h - 1) * ROWS + 2 * p); };
        auto TS  = [&](int h) { return *(const ull*)(st + (7 + h - 1) * ROWS + 2 * p); };
        auto TCN = [&](int h) { return *(const ull*)(st + (14 + h - 1) * ROWS + 2 * p); };
        auto nOf = [&](int h, int g) {
            return fma2_(TS(h), vC[g - 1], mul2_(TCN(h), vS[g - 1]));
        };
        // plain base: S += n*d/(d^2+eps)
        auto baseT = [&](int h, int g, ull& S) {
            ull d   = add2_(FX(h), vF[g - 1]);
            ull n   = nOf(h, g);
            ull den = fma2_(d, d, E2);
            S = fma2_(mul2_(n, d), rcp2_(den), S);
        };
        // base exporting w = d/(d^2+eps): S += n*w
        auto baseW = [&](int h, int g, ull& S) -> ull {
            ull d   = add2_(FX(h), vF[g - 1]);
            ull n   = nOf(h, g);
            ull den = fma2_(d, d, E2);
            ull w   = mul2_(d, rcp2_(den));
            S = fma2_(n, w, S);
            return w;
        };

        ull Sa = pk2(0.f, 0.f), Sb = pk2(0.f, 0.f);

        // ---- h = 1 ----
        ull w11 = baseW(1, 1, Sa);
        ull w12 = baseW(1, 2, Sb);
        ull w13 = baseW(1, 3, Sa);
        baseT(1, 4, Sb); baseT(1, 5, Sa); baseT(1, 6, Sb); baseT(1, 7, Sa);
        // ---- h = 2 ----
        ull w21 = baseW(2, 1, Sb);
        ull w23 = baseW(2, 3, Sa);
        baseT(2, 5, Sb); baseT(2, 7, Sa);
        ull G11 = mul2_(nOf(2, 2), IV2);                      // 2*(1,1)
        ull G12 = mul2_(nOf(2, 4), IV2);                      // 2*(1,2)
        Sb = fma2_(mul2_(nOf(2, 6), IV2), w13, Sb);           // 2*(1,3)
        // ---- h = 3 ----
        ull w31 = baseW(3, 1, Sa);
        ull w32 = baseW(3, 2, Sb);
        baseT(3, 4, Sa); baseT(3, 5, Sb); baseT(3, 7, Sa);
        G11 = fma2_(nOf(3, 3), IV3, G11);                     // 3*(1,1)
        G12 = fma2_(nOf(3, 6), IV3, G12);                     // 3*(1,2)
        Sb = fma2_(G12, w12, Sb);                             // finalize (1,2) group
        // ---- h = 4 ----
        baseT(4, 1, Sa); baseT(4, 3, Sb); baseT(4, 5, Sa); baseT(4, 7, Sb);
        ull G21 = mul2_(nOf(4, 2), IV2);                      // 2*(2,1)
        G11 = fma2_(nOf(4, 4), IV4, G11);                     // 4*(1,1)
        Sa = fma2_(mul2_(nOf(4, 6), IV2), w23, Sa);           // 2*(2,3)
        // ---- h = 5 ----
        baseT(5, 1, Sb); baseT(5, 2, Sa); baseT(5, 3, Sb);
        baseT(5, 4, Sa); baseT(5, 6, Sb); baseT(5, 7, Sa);
        G11 = fma2_(nOf(5, 5), IV5, G11);                     // 5*(1,1)
        // ---- h = 6 ----
        baseT(6, 1, Sb); baseT(6, 5, Sa); baseT(6, 7, Sb);
        Sa = fma2_(mul2_(nOf(6, 2), IV2), w31, Sa);           // 2*(3,1)
        G21 = fma2_(nOf(6, 3), IV3, G21);                     // 3*(2,1)
        Sb = fma2_(G21, w21, Sb);                             // finalize (2,1) group
        Sa = fma2_(mul2_(nOf(6, 4), IV2), w32, Sa);           // 2*(3,2)
        G11 = fma2_(nOf(6, 6), IV6, G11);                     // 6*(1,1)
        // ---- h = 7 ----
        baseT(7, 1, Sa); baseT(7, 2, Sb); baseT(7, 3, Sa);
        baseT(7, 4, Sb); baseT(7, 5, Sa); baseT(7, 6, Sb);
        G11 = fma2_(nOf(7, 7), IV7, G11);                     // 7*(1,1)
        Sa = fma2_(G11, w11, Sa);                             // finalize (1,1) group

        ull S = add2_(Sa, Sb);
        float2 s2 = upk2(S);
        int tok0 = __float_as_int(st[22 * ROWS + 2 * p]);
        int tok1 = __float_as_int(st[22 * ROWS + 2 * p + 1]);
        float k0 = s2.x + ((tok0 == v) ? st[21 * ROWS + 2 * p] : 0.f);
        gK[(size_t)r0 * NVOC + v] = k0;
        if (r0 + 1 < cnt) {
            float k1 = s2.y + ((tok1 == v) ? st[21 * ROWS + 2 * p + 1] : 0.f);
            gK[(size_t)(r0 + 1) * NVOC + v] = k1;
        }
    }
}

// ---------------- 3: HALF-chunk totals (float4 gathers from K) -------
// grid (EVT, NHC-2, NB) = 560 blocks of 200 threads — R10's validated
// best shape for this kernel. Last 2 halves (chunk 7) never consumed.
__global__ __launch_bounds__(ETPB) void k_ctot(const int* __restrict__ ids) {
    __shared__ int xid[HCH];
    int b = blockIdx.z, hc = blockIdx.y;
    int v4 = blockIdx.x * ETPB + threadIdx.x;   // < 2000 (exact)
    if (threadIdx.x < HCH)
        xid[threadIdx.x] = gMap[ids[b * NT + hc * HCH + threadIdx.x]];
    __syncthreads();
    float4 s = make_float4(0.f, 0.f, 0.f, 0.f);
#pragma unroll 1
    for (int t0 = 0; t0 < HCH; t0 += 8) {
        float4 vb[8];
#pragma unroll
        for (int j = 0; j < 8; j++)
            vb[j] = *(const float4*)(gK + (size_t)xid[t0 + j] * NVOC + 4 * v4);
#pragma unroll
        for (int j = 0; j < 8; j++) {
            s.x += vb[j].x; s.y += vb[j].y; s.z += vb[j].z; s.w += vb[j].w;
        }
    }
    *(float4*)(gCS + (size_t)(b * NHC + hc) * NVOC + 4 * v4) = s;
}

// ---------------- 4: final — float4 gathers + cumsum + offsets -------
// grid (EVT, NCH, NB) = 320 blocks of 200 threads (R9's validated best
// shape). Offset = sum of the 2c preceding half-chunk totals (L2-hot).
__global__ __launch_bounds__(ETPB) void k_final(float* __restrict__ out,
                                                const int* __restrict__ ids) {
    __shared__ int xid[LCH];
    int b = blockIdx.z, c = blockIdx.y;
    int v4 = blockIdx.x * ETPB + threadIdx.x;
    if (threadIdx.x < LCH)
        xid[threadIdx.x] = gMap[ids[b * NT + c * LCH + threadIdx.x]];
    __syncthreads();
    float4 acc = make_float4(0.f, 0.f, 0.f, 0.f);
#pragma unroll 1
    for (int hp = 0; hp < 2 * c; hp++) {      // <=14 independent L2 loads
        float4 o = *(const float4*)(gCS + (size_t)(b * NHC + hp) * NVOC + 4 * v4);
        acc.x += o.x; acc.y += o.y; acc.z += o.z; acc.w += o.w;
    }
    float* op = out + ((size_t)(b * NT + c * LCH)) * NVOC + 4 * v4;
#pragma unroll 1
    for (int t0 = 0; t0 < LCH; t0 += 8) {
        float4 vb[8];
#pragma unroll
        for (int j = 0; j < 8; j++)
            vb[j] = *(const float4*)(gK + (size_t)xid[t0 + j] * NVOC + 4 * v4);
#pragma unroll
        for (int j = 0; j < 8; j++) {
            *(float4*)op = acc; op += NVOC;
            acc.x += vb[j].x; acc.y += vb[j].y; acc.z += vb[j].z; acc.w += vb[j].w;
        }
    }
}

// ---------------- launch ---------------------------------------------
extern "C" void kernel_launch(void* const* d_in, const int* in_sizes, int n_in,
                              void* d_out, int out_size) {
    const int*   ids   = (const int*)d_in[0];
    const float* freq  = (const float*)d_in[1];
    const float* amp   = (const float*)d_in[2];
    const float* decay = (const float*)d_in[3];
    // d_in[4] = chunk_size: affects only reference's internal map chunking; result-invariant.
    float* out = (float*)d_out;

    k_init<<<1, 1024>>>(ids);                               // 0
    k_prep<<<(NVOC + 127) / 128, 128>>>(freq, amp, decay);  // 1

    dim3 gdist(VTILES, BT / ROWS);
    k_dist<<<gdist, TPB>>>();                               // 2

    dim3 gct(EVT, NHC - 2, NB);
    k_ctot<<<gct, ETPB>>>(ids);                             // 3 <- profiled slot

    dim3 gfin(EVT, NCH, NB);
    k_final<<<gfin, ETPB>>>(out, ids);                      // 4
}

// round 13
// speedup vs baseline: 1.0319x; 1.0140x over previous
#include <cuda_runtime.h>
#include <math.h>

// Problem shape (fixed for this dataset instance)
#define NB   4
#define NT   512
#define NVOC 8000
#define NH   7
#define BT   (NB * NT)           // 2048

#define LCH  64                  // k_final chunk length
#define NCH  (NT / LCH)          // 8
#define HCH  32                  // k_ctot half-chunk length
#define NHC  (NT / HCH)          // 16 (last 2 halves never consumed)

#define TPB    160
#define VTILES (NVOC / TPB)      // 50

// epilogue shape: float4 columns, 8000/4 = 2000 = 10 * 200
#define ETPB   200
#define EVT    10

#define ROWS 32                  // distinct-token rows per k_dist block
#define DLT  1e-6f               // |d| clamp: rcp -> 0 (diagonal/collisions)
#define DLT2 1e-12f              // product-guard for shared reciprocals

typedef unsigned long long ull;

// ---------------- f32x2 packed helpers (sm_103a native) --------------
__device__ __forceinline__ ull pk2(float lo, float hi) {
    ull r; asm("mov.b64 %0, {%1, %2};" : "=l"(r) : "f"(lo), "f"(hi)); return r;
}
__device__ __forceinline__ float2 upk2(ull a) {
    float2 r; asm("mov.b64 {%0, %1}, %2;" : "=f"(r.x), "=f"(r.y) : "l"(a)); return r;
}
__device__ __forceinline__ ull add2_(ull a, ull b) {
    ull r; asm("add.rn.f32x2 %0, %1, %2;" : "=l"(r) : "l"(a), "l"(b)); return r;
}
__device__ __forceinline__ ull mul2_(ull a, ull b) {
    ull r; asm("mul.rn.f32x2 %0, %1, %2;" : "=l"(r) : "l"(a), "l"(b)); return r;
}
__device__ __forceinline__ ull fma2_(ull a, ull b, ull c) {
    ull r; asm("fma.rn.f32x2 %0, %1, %2, %3;" : "=l"(r) : "l"(a), "l"(b), "l"(c)); return r;
}
__device__ __forceinline__ float rcpf(float x) {
    float r; asm("rcp.approx.ftz.f32 %0, %1;" : "=f"(r) : "f"(x)); return r;
}
// guarded packed reciprocal: lane -> 1/x, but 0 when |x| < thr
__device__ __forceinline__ ull grcp2(ull a, float thr) {
    float2 t = upk2(a);
    float r0 = rcpf(t.x);
    float r1 = rcpf(t.y);
    r0 = (fabsf(t.x) < thr) ? 0.f : r0;   // FSETP+FSEL, alu pipe
    r1 = (fabsf(t.y) < thr) ? 0.f : r1;
    return pk2(r0, r1);
}

// ---------------- device scratch (no allocs allowed) ----------------
__device__ float gVnF[NH * NVOC];        // -(2*pi*f_v*h')
__device__ float gVS[NH * NVOC];         // 2*A_vh' * sin(F)
__device__ float gVC[NH * NVOC];         // 2*A_vh' * cos(F)
// distinct-token table, comp-major [24][BT]:
// 0..6 F, 7..13 A*sin, 14..20 -A*cos, 21 dv, 22 token-as-bits, 23 pad
__device__ float gTC[24 * BT];
__device__ int   gMap[NVOC];             // token -> compact id (-1 none, -2 marked)
__device__ int   gCnt;                   // number of distinct tokens this run
__device__ float gK[(size_t)BT * NVOC];  // K[xid][v] table (worst case 65.5 MB)
__device__ float gCS[NB * NHC * NVOC];   // per-HALF-chunk totals

// ---------------- 0: reset + mark in one single-block kernel ---------
__global__ void k_init(const int* __restrict__ ids) {
    int tid = threadIdx.x;
    for (int i = tid; i < NVOC; i += blockDim.x) gMap[i] = -1;
    if (tid == 0) gCnt = 0;
    __syncthreads();                     // reset complete before marking
    for (int i = tid; i < BT; i += blockDim.x) gMap[ids[i]] = -2;
}

// ---------------- 1: vocab tables + compact ids + token tables -------
// trig: exact double range reduction (3 DP ops) + float sinpi/cospi —
// avoids the FP64 sincos software path entirely.
__global__ void k_prep(const float* __restrict__ freq,
                       const float* __restrict__ amp,
                       const float* __restrict__ decay) {
    int v = blockIdx.x * blockDim.x + threadIdx.x;
    if (v >= NVOC) return;
    float f = freq[v], A = amp[v], dec = decay[0];
    // log2(h) for h = 1..7 (compile-time constants)
    const float L2H[NH] = {0.f, 1.f, 1.5849625007f, 2.f,
                           2.3219280949f, 2.5849625007f, 2.8073549221f};
    double fd = (double)f;
    float Fh[NH], Sh[NH], Ch[NH];
    float dv = 0.f;
#pragma unroll
    for (int h = 1; h <= NH; h++) {
        double x = fd * (double)h;
        double r = x - rint(x);              // exact frac in [-0.5, 0.5]
        float rf = 2.0f * (float)r;
        float s = sinpif(rf);                // sin(2*pi*f*h)
        float c = cospif(rf);
        float F = (float)(6.283185307179586 * x);
        float Ah2 = 2.0f * A * exp2f(-dec * L2H[h - 1]);  // 2*A/h^dec
        int i = (h - 1) * NVOC + v;
        float vs = Ah2 * s, vc = Ah2 * c;
        gVnF[i] = -F;
        gVS[i]  = vs;
        gVC[i]  = vc;
        Fh[h - 1] = F;
        Sh[h - 1] = 0.5f * vs;       // A*sin (token side, no factor 2)
        Ch[h - 1] = -0.5f * vc;      // -A*cos
        dv += 0.5f * Ah2 * Ah2;      // sum_h 2*(A/h^dec)^2
    }
    if (gMap[v] == -2) {             // this vocab entry occurs as a token
        int id = atomicAdd(&gCnt, 1);
        gMap[v] = id;
#pragma unroll
        for (int h = 0; h < NH; h++) {
            gTC[h * BT + id]        = Fh[h];
            gTC[(7 + h) * BT + id]  = Sh[h];
            gTC[(14 + h) * BT + id] = Ch[h];
        }
        gTC[21 * BT + id] = dv;
        gTC[22 * BT + id] = __int_as_float(v);
    }
}

// ---------------- 2: heavy kernel — K[xid][v] for distinct tokens ----
// term = n * grcp(d): direct guarded reciprocal (diagonal/collision
// lanes -> 0, restored by dv). 4 baseT pairs share one reciprocal via
// (n0 d1 + n1 d0) * rcp(d0 d1), balancing FMA (497 rt) vs MUFU (496 rt)
// per packed iteration — both pipes co-saturated.
__global__ __launch_bounds__(TPB) void k_dist() {
    __shared__ __align__(16) float st[24 * ROWS];
    int base = blockIdx.y * ROWS;
    int cnt = gCnt;
    if (base >= cnt) return;
    int v = blockIdx.x * TPB + threadIdx.x;   // always < NVOC (exact tiling)

    // stage 24 comps x ROWS rows (comp-major both sides), vectorized
    for (int i = threadIdx.x; i < 24 * ROWS / 4; i += TPB) {
        int comp = i >> 3, q = i & 7;         // ROWS/4 == 8
        ((float4*)st)[i] = ((const float4*)(gTC + comp * BT + base))[q];
    }

    // vocab-side values: broadcast-packed registers
    ull vF[NH], vS[NH], vC[NH];
#pragma unroll
    for (int g = 0; g < NH; g++) {
        float nf = gVnF[g * NVOC + v];
        float s  = gVS[g * NVOC + v];
        float cc = gVC[g * NVOC + v];
        vF[g] = pk2(nf, nf);
        vS[g] = pk2(s, s);
        vC[g] = pk2(cc, cc);
    }
    const ull IV2 = pk2(0.5f, 0.5f);
    const ull IV3 = pk2(1.f / 3.f, 1.f / 3.f);
    const ull IV4 = pk2(0.25f, 0.25f);
    const ull IV5 = pk2(0.2f, 0.2f);
    const ull IV6 = pk2(1.f / 6.f, 1.f / 6.f);
    const ull IV7 = pk2(1.f / 7.f, 1.f / 7.f);
    __syncthreads();

    for (int p = 0; p < ROWS / 2; p++) {
        int r0 = base + 2 * p;
        if (r0 >= cnt) break;

        auto FX  = [&](int h) { return *(const ull*)(st + (h - 1) * ROWS + 2 * p); };
        auto TS  = [&](int h) { return *(const ull*)(st + (7 + h - 1) * ROWS + 2 * p); };
        auto TCN = [&](int h) { return *(const ull*)(st + (14 + h - 1) * ROWS + 2 * p); };
        auto nOf = [&](int h, int g) {
            return fma2_(TS(h), vC[g - 1], mul2_(TCN(h), vS[g - 1]));
        };
        // plain base: S += n * grcp(d)
        auto baseT = [&](int h, int g, ull& S) {
            ull d = add2_(FX(h), vF[g - 1]);
            ull n = nOf(h, g);
            S = fma2_(n, grcp2(d, DLT), S);
        };
        // base exporting w = grcp(d): S += n*w
        auto baseW = [&](int h, int g, ull& S) -> ull {
            ull d = add2_(FX(h), vF[g - 1]);
            ull n = nOf(h, g);
            ull w = grcp2(d, DLT);
            S = fma2_(n, w, S);
            return w;
        };
        // two pairs sharing one reciprocal: n0/d0 + n1/d1
        auto baseT2 = [&](int h0, int g0, int h1, int g1, ull& S) {
            ull d0 = add2_(FX(h0), vF[g0 - 1]);
            ull n0 = nOf(h0, g0);
            ull d1 = add2_(FX(h1), vF[g1 - 1]);
            ull n1 = nOf(h1, g1);
            ull q  = fma2_(n1, d0, mul2_(n0, d1));
            ull P  = mul2_(d0, d1);
            S = fma2_(q, grcp2(P, DLT2), S);
        };

        ull Sa = pk2(0.f, 0.f), Sb = pk2(0.f, 0.f);

        // ---- h = 1 ----
        ull w11 = baseW(1, 1, Sa);
        ull w12 = baseW(1, 2, Sb);
        ull w13 = baseW(1, 3, Sa);
        baseT2(1, 4, 1, 5, Sb);
        baseT2(1, 6, 1, 7, Sa);
        // ---- h = 2 ----
        ull w21 = baseW(2, 1, Sb);
        ull w23 = baseW(2, 3, Sa);
        baseT(2, 5, Sb); baseT(2, 7, Sa);
        ull G11 = mul2_(nOf(2, 2), IV2);                      // 2*(1,1)
        ull G12 = mul2_(nOf(2, 4), IV2);                      // 2*(1,2)
        Sb = fma2_(mul2_(nOf(2, 6), IV2), w13, Sb);           // 2*(1,3)
        // ---- h = 3 ----
        ull w31 = baseW(3, 1, Sa);
        ull w32 = baseW(3, 2, Sb);
        baseT(3, 4, Sa); baseT(3, 5, Sb); baseT(3, 7, Sa);
        G11 = fma2_(nOf(3, 3), IV3, G11);                     // 3*(1,1)
        G12 = fma2_(nOf(3, 6), IV3, G12);                     // 3*(1,2)
        Sb = fma2_(G12, w12, Sb);                             // finalize (1,2) group
        // ---- h = 4 ----
        baseT(4, 1, Sa); baseT(4, 3, Sb); baseT(4, 5, Sa); baseT(4, 7, Sb);
        ull G21 = mul2_(nOf(4, 2), IV2);                      // 2*(2,1)
        G11 = fma2_(nOf(4, 4), IV4, G11);                     // 4*(1,1)
        Sa = fma2_(mul2_(nOf(4, 6), IV2), w23, Sa);           // 2*(2,3)
        // ---- h = 5 ----
        baseT2(5, 1, 5, 2, Sb);
        baseT2(5, 3, 5, 4, Sa);
        baseT(5, 6, Sb); baseT(5, 7, Sa);
        G11 = fma2_(nOf(5, 5), IV5, G11);                     // 5*(1,1)
        // ---- h = 6 ----
        baseT(6, 1, Sb); baseT(6, 5, Sa); baseT(6, 7, Sb);
        Sa = fma2_(mul2_(nOf(6, 2), IV2), w31, Sa);           // 2*(3,1)
        G21 = fma2_(nOf(6, 3), IV3, G21);                     // 3*(2,1)
        Sb = fma2_(G21, w21, Sb);                             // finalize (2,1) group
        Sa = fma2_(mul2_(nOf(6, 4), IV2), w32, Sa);           // 2*(3,2)
        G11 = fma2_(nOf(6, 6), IV6, G11);                     // 6*(1,1)
        // ---- h = 7 ----
        baseT(7, 1, Sa); baseT(7, 2, Sb); baseT(7, 3, Sa);
        baseT(7, 4, Sb); baseT(7, 5, Sa); baseT(7, 6, Sb);
        G11 = fma2_(nOf(7, 7), IV7, G11);                     // 7*(1,1)
        Sa = fma2_(G11, w11, Sa);                             // finalize (1,1) group

        ull S = add2_(Sa, Sb);
        float2 s2 = upk2(S);
        int tok0 = __float_as_int(st[22 * ROWS + 2 * p]);
        int tok1 = __float_as_int(st[22 * ROWS + 2 * p + 1]);
        float k0 = s2.x + ((tok0 == v) ? st[21 * ROWS + 2 * p] : 0.f);
        gK[(size_t)r0 * NVOC + v] = k0;
        if (r0 + 1 < cnt) {
            float k1 = s2.y + ((tok1 == v) ? st[21 * ROWS + 2 * p + 1] : 0.f);
            gK[(size_t)(r0 + 1) * NVOC + v] = k1;
        }
    }
}

// ---------------- 3: HALF-chunk totals (float4 gathers from K) -------
// grid (EVT, NHC-2, NB) = 560 blocks of 200 threads.
__global__ __launch_bounds__(ETPB) void k_ctot(const int* __restrict__ ids) {
    __shared__ int xid[HCH];
    int b = blockIdx.z, hc = blockIdx.y;
    int v4 = blockIdx.x * ETPB + threadIdx.x;   // < 2000 (exact)
    if (threadIdx.x < HCH)
        xid[threadIdx.x] = gMap[ids[b * NT + hc * HCH + threadIdx.x]];
    __syncthreads();
    float4 s = make_float4(0.f, 0.f, 0.f, 0.f);
#pragma unroll 1
    for (int t0 = 0; t0 < HCH; t0 += 8) {
        float4 vb[8];
#pragma unroll
        for (int j = 0; j < 8; j++)
            vb[j] = *(const float4*)(gK + (size_t)xid[t0 + j] * NVOC + 4 * v4);
#pragma unroll
        for (int j = 0; j < 8; j++) {
            s.x += vb[j].x; s.y += vb[j].y; s.z += vb[j].z; s.w += vb[j].w;
        }
    }
    *(float4*)(gCS + (size_t)(b * NHC + hc) * NVOC + 4 * v4) = s;
}

// ---------------- 4: final — float4 gathers + cumsum + offsets -------
// grid (EVT, NCH, NB) = 320 blocks of 200 threads.
__global__ __launch_bounds__(ETPB) void k_final(float* __restrict__ out,
                                                const int* __restrict__ ids) {
    __shared__ int xid[LCH];
    int b = blockIdx.z, c = blockIdx.y;
    int v4 = blockIdx.x * ETPB + threadIdx.x;
    if (threadIdx.x < LCH)
        xid[threadIdx.x] = gMap[ids[b * NT + c * LCH + threadIdx.x]];
    __syncthreads();
    float4 acc = make_float4(0.f, 0.f, 0.f, 0.f);
#pragma unroll 1
    for (int hp = 0; hp < 2 * c; hp++) {      // <=14 independent L2 loads
        float4 o = *(const float4*)(gCS + (size_t)(b * NHC + hp) * NVOC + 4 * v4);
        acc.x += o.x; acc.y += o.y; acc.z += o.z; acc.w += o.w;
    }
    float* op = out + ((size_t)(b * NT + c * LCH)) * NVOC + 4 * v4;
#pragma unroll 1
    for (int t0 = 0; t0 < LCH; t0 += 8) {
        float4 vb[8];
#pragma unroll
        for (int j = 0; j < 8; j++)
            vb[j] = *(const float4*)(gK + (size_t)xid[t0 + j] * NVOC + 4 * v4);
#pragma unroll
        for (int j = 0; j < 8; j++) {
            *(float4*)op = acc; op += NVOC;
            acc.x += vb[j].x; acc.y += vb[j].y; acc.z += vb[j].z; acc.w += vb[j].w;
        }
    }
}

// ---------------- launch ---------------------------------------------
extern "C" void kernel_launch(void* const* d_in, const int* in_sizes, int n_in,
                              void* d_out, int out_size) {
    const int*   ids   = (const int*)d_in[0];
    const float* freq  = (const float*)d_in[1];
    const float* amp   = (const float*)d_in[2];
    const float* decay = (const float*)d_in[3];
    // d_in[4] = chunk_size: affects only reference's internal map chunking; result-invariant.
    float* out = (float*)d_out;

    k_init<<<1, 1024>>>(ids);                               // 0
    k_prep<<<(NVOC + 127) / 128, 128>>>(freq, amp, decay);  // 1

    dim3 gdist(VTILES, BT / ROWS);
    k_dist<<<gdist, TPB>>>();                               // 2

    dim3 gct(EVT, NHC - 2, NB);
    k_ctot<<<gct, ETPB>>>(ids);                             // 3 <- profiled slot

    dim3 gfin(EVT, NCH, NB);
    k_final<<<gfin, ETPB>>>(out, ids);                      // 4
}